// round 5
// baseline (speedup 1.0000x reference)
#include <cuda_runtime.h>

// ---------------------------------------------------------------------------
// MOE_DISTRIBUTE_CASCADE_GRAPH
//   inv[i]   = stable counting-sort rank of expert_ids.flat[i]   (N = B*K)
//   out[b,h] = sum_k scales[b,k] * G[inv[b*K+k], h]
//   output   = (out, out) concatenated (2*B*H floats)
// ---------------------------------------------------------------------------

#define NBINS   256        // max experts supported (dataset uses 64)
#define RWARPS  32         // warps in the rank block
#define RTHREADS (RWARPS * 32)
#define MAXN    65536      // max B*K supported (dataset uses 32768)

__device__ int g_inv[MAXN];

// --- Kernel 1: fused stable counting-sort rank (single block) ---------------
// No atomics (match-based leader RMW) and NO register prefetch (the R3/R4
// myid[32] arrays spilled to local memory under the 64-reg cap — that was
// the regression). ids are read in-loop; pass 2 re-reads them from L1.
__global__ void __launch_bounds__(RTHREADS, 1)
rank_fused_kernel(const int* __restrict__ ids, int n) {
    __shared__ int cnt[RWARPS * NBINS];   // running counters -> bases
    __shared__ int totals[NBINS];
    __shared__ int totals2[NBINS];

    const int tid  = threadIdx.x;
    const int w    = tid >> 5;
    const int lane = tid & 31;
    const int cpw  = (n + RWARPS - 1) / RWARPS;   // elems per warp chunk
    const int beg  = w * cpw;
    const int end  = min(beg + cpw, n);

    for (int i = tid; i < RWARPS * NBINS; i += RTHREADS) cnt[i] = 0;
    __syncthreads();

    int* mycnt = &cnt[w * NBINS];

    // ---- Pass 1: warp-local stable ranks + per-warp counts (match-based)
    for (int i = beg + lane; __any_sync(0xffffffffu, i < end); i += 32) {
        const bool valid = (i < end);
        const int  key   = valid ? ids[i] : (NBINS + lane); // singletons if invalid
        const unsigned mask = __match_any_sync(0xffffffffu, key);
        const int lower  = __popc(mask & ((1u << lane) - 1u));
        const int leader = __ffs(mask) - 1;
        int c0 = 0;
        if (valid && lane == leader) {
            c0 = mycnt[key];
            mycnt[key] = c0 + __popc(mask);
        }
        c0 = __shfl_sync(0xffffffffu, c0, leader);
        if (valid) g_inv[i] = c0 + lower;   // warp-local rank for now
        __syncwarp();
    }
    __syncthreads();

    // ---- Scan 1: per-expert exclusive scan over the 32 warp rows (SMEM)
    if (tid < NBINS) {
        int run = 0;
        #pragma unroll
        for (int ww = 0; ww < RWARPS; ww++) {
            const int h = cnt[ww * NBINS + tid];
            cnt[ww * NBINS + tid] = run;
            run += h;
        }
        totals[tid] = run;
    }
    __syncthreads();

    // ---- Scan 2: inclusive Hillis-Steele over expert totals
    #pragma unroll
    for (int d = 1; d < NBINS; d <<= 1) {
        int v = 0;
        if (tid < NBINS) v = (tid >= d) ? totals[tid - d] : 0;
        __syncthreads();
        if (tid < NBINS) totals2[tid] = totals[tid] + v;
        __syncthreads();
        if (tid < NBINS) totals[tid] = totals2[tid];
        __syncthreads();
    }
    if (tid < NBINS) {
        const int base = (tid == 0) ? 0 : totals[tid - 1];
        #pragma unroll
        for (int ww = 0; ww < RWARPS; ww++)
            cnt[ww * NBINS + tid] += base;
    }
    __syncthreads();

    // ---- Pass 2: add global bases (ids re-read hit L1; iterations independent)
    #pragma unroll 8
    for (int i = beg + lane; i < end; i += 32)
        g_inv[i] += mycnt[ids[i]];
}

// --- Kernel 2: gather-reduce combine (HBM streaming roofline kernel) --------
// 256 threads, 4 blocks/SM; each thread owns TWO float4 columns (h0, h0+256)
// -> 16 independent gathers in flight per thread (~8KB outstanding per SM,
// up from 4KB) to cover more of the DRAM bandwidth-delay product.
template <int K>
__global__ void __launch_bounds__(256, 4)
combine_kernel(const float* __restrict__ G,
               const float* __restrict__ scales,
               float* __restrict__ out,
               int B, int H4, int dup) {
    const int b  = blockIdx.y;
    const int h0 = blockIdx.x * 512 + threadIdx.x;
    const int h1 = h0 + 256;
    __shared__ int   rows[K];
    __shared__ float sc[K];
    if (threadIdx.x < K) {
        rows[threadIdx.x] = g_inv[b * K + threadIdx.x];
        sc[threadIdx.x]   = scales[b * K + threadIdx.x];
    }
    __syncthreads();

    const float4* __restrict__ Gv = reinterpret_cast<const float4*>(G);
    float4* __restrict__ ov = reinterpret_cast<float4*>(out);

    const bool v0 = (h0 < H4), v1 = (h1 < H4);
    float4 acc0 = make_float4(0.f, 0.f, 0.f, 0.f);
    float4 acc1 = make_float4(0.f, 0.f, 0.f, 0.f);
    #pragma unroll
    for (int k = 0; k < K; k++) {
        const float  s = sc[k];
        const size_t rb = (size_t)rows[k] * H4;
        if (v0) {
            const float4 a = __ldg(&Gv[rb + h0]);
            acc0.x = fmaf(s, a.x, acc0.x);
            acc0.y = fmaf(s, a.y, acc0.y);
            acc0.z = fmaf(s, a.z, acc0.z);
            acc0.w = fmaf(s, a.w, acc0.w);
        }
        if (v1) {
            const float4 c = __ldg(&Gv[rb + h1]);
            acc1.x = fmaf(s, c.x, acc1.x);
            acc1.y = fmaf(s, c.y, acc1.y);
            acc1.z = fmaf(s, c.z, acc1.z);
            acc1.w = fmaf(s, c.w, acc1.w);
        }
    }
    const size_t ob = (size_t)b * H4;
    if (v0) ov[ob + h0] = acc0;
    if (v1) ov[ob + h1] = acc1;
    if (dup) {
        const size_t od = (size_t)B * H4 + ob;
        if (v0) ov[od + h0] = acc0;
        if (v1) ov[od + h1] = acc1;
    }
}

// generic-K fallback
__global__ void __launch_bounds__(256, 4)
combine_kernel_gen(const float* __restrict__ G,
                   const float* __restrict__ scales,
                   float* __restrict__ out,
                   int B, int K, int H4, int dup) {
    const int b = blockIdx.y;
    const int h = blockIdx.x * 256 + threadIdx.x;
    __shared__ int   rows[32];
    __shared__ float sc[32];
    if (threadIdx.x < (unsigned)K) {
        rows[threadIdx.x] = g_inv[b * K + threadIdx.x];
        sc[threadIdx.x]   = scales[b * K + threadIdx.x];
    }
    __syncthreads();
    if (h >= H4) return;

    const float4* __restrict__ Gv = reinterpret_cast<const float4*>(G);
    float4* __restrict__ ov = reinterpret_cast<float4*>(out);

    float4 acc = make_float4(0.f, 0.f, 0.f, 0.f);
    for (int k = 0; k < K; k++) {
        const float  s = sc[k];
        const float4 v = __ldg(&Gv[(size_t)rows[k] * H4 + h]);
        acc.x = fmaf(s, v.x, acc.x);
        acc.y = fmaf(s, v.y, acc.y);
        acc.z = fmaf(s, v.z, acc.z);
        acc.w = fmaf(s, v.w, acc.w);
    }
    const size_t o = (size_t)b * H4 + h;
    ov[o] = acc;
    if (dup) ov[(size_t)B * H4 + o] = acc;
}

// ---------------------------------------------------------------------------
extern "C" void kernel_launch(void* const* d_in, const int* in_sizes, int n_in,
                              void* d_out, int out_size) {
    // metadata order: x[B,H] f32, expert_ids[B,K] i32, expert_scales[B,K] f32,
    //                 golden_expand_x[B*K,H] f32, moe_expert_num i32
    const int*   ids    = (const int*)  d_in[1];
    const float* scales = (const float*)d_in[2];
    const float* G      = (const float*)d_in[3];
    float*       out    = (float*)d_out;

    const int N  = in_sizes[1];                     // B*K = 32768
    const long long GH = (long long)in_sizes[3];    // N*H
    const int H  = (int)(GH / N);                   // 4096
    const int B  = in_sizes[0] / H;                 // 4096
    const int K  = N / B;                           // 8
    const int H4 = H >> 2;
    const int dup = (out_size >= 2 * B * H) ? 1 : 0;

    rank_fused_kernel<<<1, RTHREADS>>>(ids, N);

    if (K == 8) {
        const int cpb = (H4 + 511) / 512;           // 512 float4 cols per block
        dim3 grid(cpb, B);
        combine_kernel<8><<<grid, 256>>>(G, scales, out, B, H4, dup);
    } else {
        const int cpb = (H4 + 255) / 256;
        dim3 grid(cpb, B);
        combine_kernel_gen<<<grid, 256>>>(G, scales, out, B, K, H4, dup);
    }
}

// round 6
// speedup vs baseline: 1.0212x; 1.0212x over previous
#include <cuda_runtime.h>

// ---------------------------------------------------------------------------
// MOE_DISTRIBUTE_CASCADE_GRAPH
//   inv[i]   = stable counting-sort rank of expert_ids.flat[i]   (N = B*K)
//   out[b,h] = sum_k scales[b,k] * G[inv[b*K+k], h]
//   output   = (out, out) concatenated (2*B*H floats)
// ---------------------------------------------------------------------------

#define NBINS   256        // max experts supported (dataset uses 64)
#define RWARPS  32         // warps in the rank block
#define RTHREADS (RWARPS * 32)
#define MAXN    65536      // max B*K supported (dataset uses 32768)

__device__ int g_inv[MAXN];

// Process one id in the match-based stable-rank scheme.
__device__ __forceinline__ void rank_step(int id, int idx, int lane,
                                          int* mycnt) {
    const unsigned FULL = 0xffffffffu;
    const bool valid = (id >= 0);
    const int  key   = valid ? id : (NBINS + lane);    // singleton if invalid
    const unsigned mask = __match_any_sync(FULL, key);
    const int lower  = __popc(mask & ((1u << lane) - 1u));
    const int leader = __ffs(mask) - 1;
    int c0 = 0;
    if (valid && lane == leader) {
        c0 = mycnt[key];
        mycnt[key] = c0 + __popc(mask);
    }
    c0 = __shfl_sync(FULL, c0, leader);
    if (valid) g_inv[idx] = c0 + lower;                // warp-local rank
    __syncwarp();                                      // order SMEM RMWs
}

// --- Kernel 1: fused stable counting-sort rank (single block) ---------------
// Pass 1 uses a counted loop with a manual depth-4 load pipeline: the next
// group's 4 independent LDGs are issued before the current group's match
// chains, so the ~600-cycle DRAM latency overlaps the ~500-cycle chain.
__global__ void __launch_bounds__(RTHREADS, 1)
rank_fused_kernel(const int* __restrict__ ids, int n) {
    __shared__ int cnt[RWARPS * NBINS];   // running counters -> bases
    __shared__ int totals[NBINS];
    __shared__ int totals2[NBINS];

    const int tid  = threadIdx.x;
    const int w    = tid >> 5;
    const int lane = tid & 31;
    const int cpw  = (n + RWARPS - 1) / RWARPS;   // elems per warp chunk
    const int beg  = w * cpw;
    const int end  = min(beg + cpw, n);

    for (int i = tid; i < RWARPS * NBINS; i += RTHREADS) cnt[i] = 0;
    __syncthreads();

    int* mycnt = &cnt[w * NBINS];

    // ---- Pass 1: warp-local stable ranks + per-warp counts, pipelined ------
    {
        int i = beg + lane;
        int a0 = (i       < end) ? __ldg(&ids[i])       : -1;
        int a1 = (i + 32  < end) ? __ldg(&ids[i + 32])  : -1;
        int a2 = (i + 64  < end) ? __ldg(&ids[i + 64])  : -1;
        int a3 = (i + 96  < end) ? __ldg(&ids[i + 96])  : -1;
        for (int base = beg; base < end; base += 128) {
            // issue next group's loads before consuming this group
            const int j = i + 128;
            const int b0 = (j       < end) ? __ldg(&ids[j])       : -1;
            const int b1 = (j + 32  < end) ? __ldg(&ids[j + 32])  : -1;
            const int b2 = (j + 64  < end) ? __ldg(&ids[j + 64])  : -1;
            const int b3 = (j + 96  < end) ? __ldg(&ids[j + 96])  : -1;
            rank_step(a0, i,      lane, mycnt);
            rank_step(a1, i + 32, lane, mycnt);
            rank_step(a2, i + 64, lane, mycnt);
            rank_step(a3, i + 96, lane, mycnt);
            a0 = b0; a1 = b1; a2 = b2; a3 = b3;
            i = j;
        }
    }
    __syncthreads();

    // ---- Scan 1: per-expert exclusive scan over the 32 warp rows (SMEM) ----
    if (tid < NBINS) {
        int run = 0;
        #pragma unroll
        for (int ww = 0; ww < RWARPS; ww++) {
            const int h = cnt[ww * NBINS + tid];
            cnt[ww * NBINS + tid] = run;
            run += h;
        }
        totals[tid] = run;
    }
    __syncthreads();

    // ---- Scan 2: inclusive Hillis-Steele over expert totals ----------------
    #pragma unroll
    for (int d = 1; d < NBINS; d <<= 1) {
        int v = 0;
        if (tid < NBINS) v = (tid >= d) ? totals[tid - d] : 0;
        __syncthreads();
        if (tid < NBINS) totals2[tid] = totals[tid] + v;
        __syncthreads();
        if (tid < NBINS) totals[tid] = totals2[tid];
        __syncthreads();
    }
    if (tid < NBINS) {
        const int base = (tid == 0) ? 0 : totals[tid - 1];
        #pragma unroll
        for (int ww = 0; ww < RWARPS; ww++)
            cnt[ww * NBINS + tid] += base;
    }
    __syncthreads();

    // ---- Pass 2: add global bases (independent iterations, ids L1-warm) ----
    #pragma unroll 8
    for (int i = beg + lane; i < end; i += 32)
        g_inv[i] += mycnt[__ldg(&ids[i])];
}

// --- Kernel 2: gather-reduce combine (HBM streaming roofline kernel) --------
// 256 threads, 4 blocks/SM, two float4 columns per thread. GUARD=false is the
// exact-fit path (H4 % 512 == 0): no bounds predication -> fewer registers.
template <int K, bool GUARD>
__global__ void __launch_bounds__(256, 4)
combine_kernel(const float* __restrict__ G,
               const float* __restrict__ scales,
               float* __restrict__ out,
               int B, int H4, int dup) {
    const int b  = blockIdx.y;
    const int h0 = blockIdx.x * 512 + threadIdx.x;
    const int h1 = h0 + 256;
    __shared__ int   rows[K];
    __shared__ float sc[K];
    if (threadIdx.x < K) {
        rows[threadIdx.x] = g_inv[b * K + threadIdx.x];
        sc[threadIdx.x]   = scales[b * K + threadIdx.x];
    }
    __syncthreads();

    const float4* __restrict__ Gv = reinterpret_cast<const float4*>(G);
    float4* __restrict__ ov = reinterpret_cast<float4*>(out);

    const bool v0 = GUARD ? (h0 < H4) : true;
    const bool v1 = GUARD ? (h1 < H4) : true;
    float4 acc0 = make_float4(0.f, 0.f, 0.f, 0.f);
    float4 acc1 = make_float4(0.f, 0.f, 0.f, 0.f);
    #pragma unroll
    for (int k = 0; k < K; k++) {
        const float  s = sc[k];
        const size_t rb = (size_t)rows[k] * H4;
        if (v0) {
            const float4 a = __ldg(&Gv[rb + h0]);
            acc0.x = fmaf(s, a.x, acc0.x);
            acc0.y = fmaf(s, a.y, acc0.y);
            acc0.z = fmaf(s, a.z, acc0.z);
            acc0.w = fmaf(s, a.w, acc0.w);
        }
        if (v1) {
            const float4 c = __ldg(&Gv[rb + h1]);
            acc1.x = fmaf(s, c.x, acc1.x);
            acc1.y = fmaf(s, c.y, acc1.y);
            acc1.z = fmaf(s, c.z, acc1.z);
            acc1.w = fmaf(s, c.w, acc1.w);
        }
    }
    const size_t ob = (size_t)b * H4;
    if (v0) ov[ob + h0] = acc0;
    if (v1) ov[ob + h1] = acc1;
    if (dup) {
        const size_t od = (size_t)B * H4 + ob;
        if (v0) ov[od + h0] = acc0;
        if (v1) ov[od + h1] = acc1;
    }
}

// generic-K fallback
__global__ void __launch_bounds__(256, 4)
combine_kernel_gen(const float* __restrict__ G,
                   const float* __restrict__ scales,
                   float* __restrict__ out,
                   int B, int K, int H4, int dup) {
    const int b = blockIdx.y;
    const int h = blockIdx.x * 256 + threadIdx.x;
    __shared__ int   rows[32];
    __shared__ float sc[32];
    if (threadIdx.x < (unsigned)K) {
        rows[threadIdx.x] = g_inv[b * K + threadIdx.x];
        sc[threadIdx.x]   = scales[b * K + threadIdx.x];
    }
    __syncthreads();
    if (h >= H4) return;

    const float4* __restrict__ Gv = reinterpret_cast<const float4*>(G);
    float4* __restrict__ ov = reinterpret_cast<float4*>(out);

    float4 acc = make_float4(0.f, 0.f, 0.f, 0.f);
    for (int k = 0; k < K; k++) {
        const float  s = sc[k];
        const float4 v = __ldg(&Gv[(size_t)rows[k] * H4 + h]);
        acc.x = fmaf(s, v.x, acc.x);
        acc.y = fmaf(s, v.y, acc.y);
        acc.z = fmaf(s, v.z, acc.z);
        acc.w = fmaf(s, v.w, acc.w);
    }
    const size_t o = (size_t)b * H4 + h;
    ov[o] = acc;
    if (dup) ov[(size_t)B * H4 + o] = acc;
}

// ---------------------------------------------------------------------------
extern "C" void kernel_launch(void* const* d_in, const int* in_sizes, int n_in,
                              void* d_out, int out_size) {
    // metadata order: x[B,H] f32, expert_ids[B,K] i32, expert_scales[B,K] f32,
    //                 golden_expand_x[B*K,H] f32, moe_expert_num i32
    const int*   ids    = (const int*)  d_in[1];
    const float* scales = (const float*)d_in[2];
    const float* G      = (const float*)d_in[3];
    float*       out    = (float*)d_out;

    const int N  = in_sizes[1];                     // B*K = 32768
    const long long GH = (long long)in_sizes[3];    // N*H
    const int H  = (int)(GH / N);                   // 4096
    const int B  = in_sizes[0] / H;                 // 4096
    const int K  = N / B;                           // 8
    const int H4 = H >> 2;
    const int dup = (out_size >= 2 * B * H) ? 1 : 0;

    rank_fused_kernel<<<1, RTHREADS>>>(ids, N);

    if (K == 8) {
        const int cpb = (H4 + 511) / 512;           // 512 float4 cols per block
        dim3 grid(cpb, B);
        if ((H4 & 511) == 0)
            combine_kernel<8, false><<<grid, 256>>>(G, scales, out, B, H4, dup);
        else
            combine_kernel<8, true><<<grid, 256>>>(G, scales, out, B, H4, dup);
    } else {
        const int cpb = (H4 + 255) / 256;
        dim3 grid(cpb, B);
        combine_kernel_gen<<<grid, 256>>>(G, scales, out, B, K, H4, dup);
    }
}